// round 15
// baseline (speedup 1.0000x reference)
#include <cuda_runtime.h>
#include <cuda_fp16.h>
#include <math.h>

#define DTSTEP 0.03125f

// Scratch: voxel-major half4 volume. B=2, D=128 -> 2*128^3 * 8B = 32 MiB.
#define VOLH_CAP (2 * 128 * 128 * 128)
__device__ uint2 g_volh[VOLH_CAP];

// ---------------------------------------------------------------------------
// Pass 1: permute [B,4,D,D,D] fp32 channel-major -> [B,D,D,D] half4 voxel-major
// ---------------------------------------------------------------------------
__global__ void permute_half_kernel(const float4* __restrict__ vol, int B, int D3) {
    int i = blockIdx.x * blockDim.x + threadIdx.x;   // voxel-group (4 voxels)
    int groups_per_b = D3 >> 2;
    int n = B * groups_per_b;
    if (i >= n) return;
    int b = i / groups_per_b;
    int r4 = i - b * groups_per_b;

    const float4* base = vol + (size_t)b * D3 + r4;
    float4 ch0 = base[0];
    float4 ch1 = base[(size_t)groups_per_b];
    float4 ch2 = base[2 * (size_t)groups_per_b];
    float4 ch3 = base[3 * (size_t)groups_per_b];

    const float* c0 = &ch0.x; const float* c1 = &ch1.x;
    const float* c2 = &ch2.x; const float* c3 = &ch3.x;

    uint2 outv[4];
    #pragma unroll
    for (int j = 0; j < 4; ++j) {
        __half2 h01 = __floats2half2_rn(c0[j], c1[j]);
        __half2 h23 = __floats2half2_rn(c2[j], c3[j]);
        outv[j].x = *reinterpret_cast<unsigned*>(&h01);
        outv[j].y = *reinterpret_cast<unsigned*>(&h23);
    }
    uint4* o = reinterpret_cast<uint4*>(g_volh + (size_t)b * D3 + (size_t)r4 * 4);
    o[0] = make_uint4(outv[0].x, outv[0].y, outv[1].x, outv[1].y);
    o[1] = make_uint4(outv[2].x, outv[2].y, outv[3].x, outv[3].y);
}

// ---------------------------------------------------------------------------
// Helpers
// ---------------------------------------------------------------------------
struct Corners {
    uint2 c000, c001, c010, c011, c100, c101, c110, c111;
};

__device__ __forceinline__ Corners load_corners(const uint2* __restrict__ g,
                                                int base, int D, int D2) {
    Corners r;
    r.c000 = __ldg(g + base);
    r.c001 = __ldg(g + base + 1);
    r.c010 = __ldg(g + base + D);
    r.c011 = __ldg(g + base + D + 1);
    r.c100 = __ldg(g + base + D2);
    r.c101 = __ldg(g + base + D2 + 1);
    r.c110 = __ldg(g + base + D2 + D);
    r.c111 = __ldg(g + base + D2 + D + 1);
    return r;
}

struct H4 { __half2 lo, hi; };  // lo = channels 0,1; hi = channels 2,3

__device__ __forceinline__ H4 u2h4(uint2 u) {
    H4 r;
    r.lo = *reinterpret_cast<__half2*>(&u.x);
    r.hi = *reinterpret_cast<__half2*>(&u.y);
    return r;
}

// lerp: a + t*(b-a) in packed half2, both lanes
__device__ __forceinline__ H4 lerpH(H4 a, H4 b, __half2 t) {
    H4 r;
    r.lo = __hfma2(t, __hsub2(b.lo, a.lo), a.lo);
    r.hi = __hfma2(t, __hsub2(b.hi, a.hi), a.hi);
    return r;
}

// full trilinear in half2; only the final value converts to fp32
__device__ __forceinline__ float4 trilerp(const Corners& c,
                                          float wx, float wy, float wz) {
    __half2 tx = __float2half2_rn(wx);
    __half2 ty = __float2half2_rn(wy);
    __half2 tz = __float2half2_rn(wz);
    H4 c00 = lerpH(u2h4(c.c000), u2h4(c.c001), tx);
    H4 c01 = lerpH(u2h4(c.c010), u2h4(c.c011), tx);
    H4 c10 = lerpH(u2h4(c.c100), u2h4(c.c101), tx);
    H4 c11 = lerpH(u2h4(c.c110), u2h4(c.c111), tx);
    H4 c0 = lerpH(c00, c01, ty);
    H4 c1 = lerpH(c10, c11, ty);
    H4 r  = lerpH(c0, c1, tz);
    float2 f01 = __half22float2(r.lo);
    float2 f23 = __half22float2(r.hi);
    return make_float4(f01.x, f01.y, f23.x, f23.y);
}

// ---------------------------------------------------------------------------
// Pass 2: one thread per pixel ray; 8x4 warp pixel tiles for gather locality;
// hand-unrolled x2 ping-pong software pipeline (no register rotation MOVs).
// Ray setup + validity use IEEE RN intrinsics (bit-match XLA on the boundary
// decision); |p|<1 via fabs/fmax is bit-equivalent to the 6 strict compares.
// ---------------------------------------------------------------------------
__global__ void __launch_bounds__(128, 8)
raymarch_kernel(const float* __restrict__ camrot,
                const float* __restrict__ campos,
                const float* __restrict__ focal,
                const float* __restrict__ princpt,
                const float* __restrict__ pix,
                float* __restrict__ out,
                int B, int H, int W, int D, int nsteps) {
    // 8x16 block tile; each warp covers an 8x4 pixel tile
    int x = blockIdx.x * 8  + (threadIdx.x & 7);
    int y = blockIdx.y * 16 + (threadIdx.x >> 3);
    int b = blockIdx.z;
    if (x >= W || y >= H) return;

    // --- camera ray (IEEE RN, matches XLA HLO op-by-op) ---
    float fx = focal[b * 2 + 0], fy = focal[b * 2 + 1];
    float px = princpt[b * 2 + 0], py = princpt[b * 2 + 1];
    size_t pidx = (((size_t)b * H + y) * W + x) * 2;
    float u = __fdiv_rn(__fsub_rn(pix[pidx + 0], px), fx);
    float v = __fdiv_rn(__fsub_rn(pix[pidx + 1], py), fy);

    const float* R = camrot + b * 9;
    float dx = __fadd_rn(__fadd_rn(__fmul_rn(R[0], u), __fmul_rn(R[3], v)), R[6]);
    float dy = __fadd_rn(__fadd_rn(__fmul_rn(R[1], u), __fmul_rn(R[4], v)), R[7]);
    float dz = __fadd_rn(__fadd_rn(__fmul_rn(R[2], u), __fmul_rn(R[5], v)), R[8]);

    float sxx = __fmul_rn(dx, dx);
    float syy = __fmul_rn(dy, dy);
    float szz = __fmul_rn(dz, dz);
    float norm = __fsqrt_rn(__fadd_rn(__fadd_rn(sxx, syy), szz));
    dx = __fdiv_rn(dx, norm);
    dy = __fdiv_rn(dy, norm);
    dz = __fdiv_rn(dz, norm);

    float cx = campos[b * 3 + 0], cy = campos[b * 3 + 1], cz = campos[b * 3 + 2];

    float t1x = __fdiv_rn(__fsub_rn(-1.0f, cx), dx);
    float t2x = __fdiv_rn(__fsub_rn( 1.0f, cx), dx);
    float t1y = __fdiv_rn(__fsub_rn(-1.0f, cy), dy);
    float t2y = __fdiv_rn(__fsub_rn( 1.0f, cy), dy);
    float t1z = __fdiv_rn(__fsub_rn(-1.0f, cz), dz);
    float t2z = __fdiv_rn(__fsub_rn( 1.0f, cz), dz);
    float tmin = fmaxf(fminf(t1x, t2x),
                 fmaxf(fminf(t1y, t2y), fminf(t1z, t2z)));
    float tmax = fminf(fmaxf(t1x, t2x),
                 fminf(fmaxf(t1y, t2y), fmaxf(t1z, t2z)));
    bool hit = tmin < tmax;

    size_t obase = ((size_t)b * 4) * H * W + (size_t)y * W + x;
    size_t cstr = (size_t)H * W;

    float r0 = 0.0f, r1 = 0.0f, r2 = 0.0f, alpha = 0.0f;

    if (hit) {
        float t0 = fmaxf(tmin, 0.0f);
        float posx = __fadd_rn(cx, __fmul_rn(dx, t0));
        float posy = __fadd_rn(cy, __fmul_rn(dy, t0));
        float posz = __fadd_rn(cz, __fmul_rn(dz, t0));
        float stepx = __fmul_rn(dx, DTSTEP);   // exact (DT = 2^-5)
        float stepy = __fmul_rn(dy, DTSTEP);
        float stepz = __fmul_rn(dz, DTSTEP);

        const float scaleD = 0.5f * (float)(D - 1);   // folded (pos+1)*0.5*(D-1)
        const int D2 = D * D;
        const int Dm2 = D - 2;
        const int vb = b * D * D2;                    // < 2^22, int is safe
        const uint2* g = g_volh;

        // |p| < 1 on all axes == (p > -1 && p < 1) on all axes, bit-exactly
        #define INSIDE (fmaxf(fabsf(posx), fmaxf(fabsf(posy), fabsf(posz))) < 1.0f)
        #define ADV do { posx = __fadd_rn(posx, stepx); \
                         posy = __fadd_rn(posy, stepy); \
                         posz = __fadd_rn(posz, stepz); } while (0)

        #define PREP_LOAD(wx_, wy_, wz_, buf_) do {                          \
            float gx_ = (posx + 1.0f) * scaleD;                              \
            float gy_ = (posy + 1.0f) * scaleD;                              \
            float gz_ = (posz + 1.0f) * scaleD;                              \
            int x0_ = min((int)gx_, Dm2);                                    \
            int y0_ = min((int)gy_, Dm2);                                    \
            int z0_ = min((int)gz_, Dm2);                                    \
            wx_ = gx_ - (float)x0_;                                          \
            wy_ = gy_ - (float)y0_;                                          \
            wz_ = gz_ - (float)z0_;                                          \
            buf_ = load_corners(g, vb + z0_ * D2 + y0_ * D + x0_, D, D2);    \
        } while (0)

        #define COMPOSITE(buf_, wx_, wy_, wz_) do {                          \
            float4 smp_ = trilerp(buf_, wx_, wy_, wz_);                      \
            float contrib_ = fminf(alpha + smp_.w * DTSTEP, 1.0f) - alpha;   \
            r0 += smp_.x * contrib_;                                         \
            r1 += smp_.y * contrib_;                                         \
            r2 += smp_.z * contrib_;                                         \
            alpha += contrib_;                                               \
        } while (0)

        // entry scan: positions monotone per axis -> valid region contiguous
        int s = 0;
        bool valid = INSIDE;
        while (!valid && (s + 1) < nsteps) {
            ADV;
            ++s;
            valid = INSIDE;
        }

        if (valid) {
            float w0x, w0y, w0z, w1x, w1y, w1z;
            Corners buf0, buf1;
            PREP_LOAD(w0x, w0y, w0z, buf0);

            for (;;) {
                // stage A: prefetch s+1 into buf1, consume buf0
                ADV; ++s;
                bool v = (s < nsteps) && INSIDE;
                if (v) PREP_LOAD(w1x, w1y, w1z, buf1);
                COMPOSITE(buf0, w0x, w0y, w0z);
                if (!v || (1.0f - alpha < 1e-6f)) break;   // exit or saturated

                // stage B: prefetch s+1 into buf0, consume buf1
                ADV; ++s;
                v = (s < nsteps) && INSIDE;
                if (v) PREP_LOAD(w0x, w0y, w0z, buf0);
                COMPOSITE(buf1, w1x, w1y, w1z);
                if (!v || (1.0f - alpha < 1e-6f)) break;
            }
        }
        #undef INSIDE
        #undef ADV
        #undef PREP_LOAD
        #undef COMPOSITE
    }

    out[obase + 0 * cstr] = r0;
    out[obase + 1 * cstr] = r1;
    out[obase + 2 * cstr] = r2;
    out[obase + 3 * cstr] = alpha;
}

// ---------------------------------------------------------------------------
// Launch
// ---------------------------------------------------------------------------
extern "C" void kernel_launch(void* const* d_in, const int* in_sizes, int n_in,
                              void* d_out, int out_size) {
    const float* camrot  = (const float*)d_in[0];
    const float* campos  = (const float*)d_in[1];
    const float* focal   = (const float*)d_in[2];
    const float* princpt = (const float*)d_in[3];
    const float* pix     = (const float*)d_in[4];
    const float* volume  = (const float*)d_in[5];
    float* out = (float*)d_out;

    int B = in_sizes[1] / 3;
    int hw = in_sizes[4] / (2 * B);
    int H = (int)(sqrt((double)hw) + 0.5);
    int W = H;
    int d3 = in_sizes[5] / (4 * B);
    int D = (int)(cbrt((double)d3) + 0.5);
    int nsteps = (int)ceil(2.0 * sqrt(3.0) / 0.03125);  // 111

    int ngroups = B * (d3 / 4);
    permute_half_kernel<<<(ngroups + 255) / 256, 256>>>(
        (const float4*)volume, B, d3);

    dim3 block(128, 1, 1);
    dim3 grid((W + 7) / 8, (H + 15) / 16, B);
    raymarch_kernel<<<grid, block>>>(camrot, campos, focal, princpt, pix,
                                     out, B, H, W, D, nsteps);
}

// round 17
// speedup vs baseline: 1.1935x; 1.1935x over previous
#include <cuda_runtime.h>
#include <cuda_fp16.h>
#include <math.h>

#define DTSTEP 0.03125f

// Scratch: voxel-major half4 volume. B=2, D=128 -> 2*128^3 * 8B = 32 MiB.
#define VOLH_CAP (2 * 128 * 128 * 128)
__device__ uint2 g_volh[VOLH_CAP];

// ---------------------------------------------------------------------------
// Pass 1: permute [B,4,D,D,D] fp32 channel-major -> [B,D,D,D] half4 voxel-major
// ---------------------------------------------------------------------------
__global__ void permute_half_kernel(const float4* __restrict__ vol, int B, int D3) {
    int i = blockIdx.x * blockDim.x + threadIdx.x;   // voxel-group (4 voxels)
    int groups_per_b = D3 >> 2;
    int n = B * groups_per_b;
    if (i >= n) return;
    int b = i / groups_per_b;
    int r4 = i - b * groups_per_b;

    const float4* base = vol + (size_t)b * D3 + r4;
    float4 ch0 = base[0];
    float4 ch1 = base[(size_t)groups_per_b];
    float4 ch2 = base[2 * (size_t)groups_per_b];
    float4 ch3 = base[3 * (size_t)groups_per_b];

    const float* c0 = &ch0.x; const float* c1 = &ch1.x;
    const float* c2 = &ch2.x; const float* c3 = &ch3.x;

    uint2 outv[4];
    #pragma unroll
    for (int j = 0; j < 4; ++j) {
        __half2 h01 = __floats2half2_rn(c0[j], c1[j]);
        __half2 h23 = __floats2half2_rn(c2[j], c3[j]);
        outv[j].x = *reinterpret_cast<unsigned*>(&h01);
        outv[j].y = *reinterpret_cast<unsigned*>(&h23);
    }
    uint4* o = reinterpret_cast<uint4*>(g_volh + (size_t)b * D3 + (size_t)r4 * 4);
    o[0] = make_uint4(outv[0].x, outv[0].y, outv[1].x, outv[1].y);
    o[1] = make_uint4(outv[2].x, outv[2].y, outv[3].x, outv[3].y);
}

// ---------------------------------------------------------------------------
// Helpers
// ---------------------------------------------------------------------------
struct Plane {                      // one z-plane: 4 corners
    uint2 c00, c01, c10, c11;       // (y0,x0) (y0,x1) (y1,x0) (y1,x1)
};

__device__ __forceinline__ Plane load_plane(const uint2* __restrict__ g,
                                            int base, int D) {
    Plane r;
    r.c00 = __ldg(g + base);
    r.c01 = __ldg(g + base + 1);
    r.c10 = __ldg(g + base + D);
    r.c11 = __ldg(g + base + D + 1);
    return r;
}

struct H4 { __half2 lo, hi; };  // lo = channels 0,1; hi = channels 2,3

__device__ __forceinline__ H4 u2h4(uint2 u) {
    H4 r;
    r.lo = *reinterpret_cast<__half2*>(&u.x);
    r.hi = *reinterpret_cast<__half2*>(&u.y);
    return r;
}

// lerp: a + t*(b-a) in packed half2, both lanes
__device__ __forceinline__ H4 lerpH(H4 a, H4 b, __half2 t) {
    H4 r;
    r.lo = __hfma2(t, __hsub2(b.lo, a.lo), a.lo);
    r.hi = __hfma2(t, __hsub2(b.hi, a.hi), a.hi);
    return r;
}

// bilinear within one z-plane: x-lerps then y-lerp (matches reference order)
__device__ __forceinline__ H4 bilerp(const Plane& p, __half2 tx, __half2 ty) {
    H4 cx0 = lerpH(u2h4(p.c00), u2h4(p.c01), tx);
    H4 cx1 = lerpH(u2h4(p.c10), u2h4(p.c11), tx);
    return lerpH(cx0, cx1, ty);
}

// ---------------------------------------------------------------------------
// Pass 2: TWO threads per pixel ray (even lane = z0 plane, odd lane = z1
// plane). Each lane loads 4 corners + does the bilinear for its plane; the
// pair exchanges results with shfl_xor and both finish the z-lerp+composite
// (bit-identical per pair -> pairs never diverge from each other). This
// doubles resident warps on a grid-capped-occupancy kernel and halves the
// per-thread load count and lerp tree.
// Ray setup + validity use IEEE RN intrinsics (bit-match XLA on the boundary
// decision); |p|<1 via fabs/fmax is bit-equivalent to the 6 strict compares.
// Lerp order x->y->z matches the reference exactly.
// ---------------------------------------------------------------------------
__global__ void __launch_bounds__(256, 6)
raymarch_kernel(const float* __restrict__ camrot,
                const float* __restrict__ campos,
                const float* __restrict__ focal,
                const float* __restrict__ princpt,
                const float* __restrict__ pix,
                float* __restrict__ out,
                int B, int H, int W, int D, int nsteps) {
    // threadIdx.x in [0,64): pixel x = tid>>1, z-plane = tid&1.
    // Warp = 16 consecutive x pixels (x stays the contiguous gather dim).
    int zpl = threadIdx.x & 1;
    int x = blockIdx.x * 32 + (threadIdx.x >> 1);
    int y = blockIdx.y * 4 + threadIdx.y;
    int b = blockIdx.z;
    if (x >= W || y >= H) return;

    // --- camera ray (IEEE RN, matches XLA HLO op-by-op) ---
    float fx = focal[b * 2 + 0], fy = focal[b * 2 + 1];
    float px = princpt[b * 2 + 0], py = princpt[b * 2 + 1];
    size_t pidx = (((size_t)b * H + y) * W + x) * 2;
    float u = __fdiv_rn(__fsub_rn(pix[pidx + 0], px), fx);
    float v = __fdiv_rn(__fsub_rn(pix[pidx + 1], py), fy);

    const float* R = camrot + b * 9;
    float dx = __fadd_rn(__fadd_rn(__fmul_rn(R[0], u), __fmul_rn(R[3], v)), R[6]);
    float dy = __fadd_rn(__fadd_rn(__fmul_rn(R[1], u), __fmul_rn(R[4], v)), R[7]);
    float dz = __fadd_rn(__fadd_rn(__fmul_rn(R[2], u), __fmul_rn(R[5], v)), R[8]);

    float sxx = __fmul_rn(dx, dx);
    float syy = __fmul_rn(dy, dy);
    float szz = __fmul_rn(dz, dz);
    float norm = __fsqrt_rn(__fadd_rn(__fadd_rn(sxx, syy), szz));
    dx = __fdiv_rn(dx, norm);
    dy = __fdiv_rn(dy, norm);
    dz = __fdiv_rn(dz, norm);

    float cx = campos[b * 3 + 0], cy = campos[b * 3 + 1], cz = campos[b * 3 + 2];

    float t1x = __fdiv_rn(__fsub_rn(-1.0f, cx), dx);
    float t2x = __fdiv_rn(__fsub_rn( 1.0f, cx), dx);
    float t1y = __fdiv_rn(__fsub_rn(-1.0f, cy), dy);
    float t2y = __fdiv_rn(__fsub_rn( 1.0f, cy), dy);
    float t1z = __fdiv_rn(__fsub_rn(-1.0f, cz), dz);
    float t2z = __fdiv_rn(__fsub_rn( 1.0f, cz), dz);
    float tmin = fmaxf(fminf(t1x, t2x),
                 fmaxf(fminf(t1y, t2y), fminf(t1z, t2z)));
    float tmax = fminf(fmaxf(t1x, t2x),
                 fminf(fmaxf(t1y, t2y), fmaxf(t1z, t2z)));
    bool hit = tmin < tmax;

    size_t obase = ((size_t)b * 4) * H * W + (size_t)y * W + x;
    size_t cstr = (size_t)H * W;

    float r0 = 0.0f, r1 = 0.0f, r2 = 0.0f, alpha = 0.0f;

    if (hit) {
        float t0 = fmaxf(tmin, 0.0f);
        float posx = __fadd_rn(cx, __fmul_rn(dx, t0));
        float posy = __fadd_rn(cy, __fmul_rn(dy, t0));
        float posz = __fadd_rn(cz, __fmul_rn(dz, t0));
        float stepx = __fmul_rn(dx, DTSTEP);   // exact (DT = 2^-5)
        float stepy = __fmul_rn(dy, DTSTEP);
        float stepz = __fmul_rn(dz, DTSTEP);

        const float scaleD = 0.5f * (float)(D - 1);   // folded (pos+1)*0.5*(D-1)
        const int D2 = D * D;
        const int Dm2 = D - 2;
        const int vb = b * D * D2;                    // < 2^22, int is safe
        const int zoff = zpl * D2;                    // my z-plane offset
        const uint2* g = g_volh;

        // |p| < 1 on all axes == (p > -1 && p < 1) on all axes, bit-exactly
        #define INSIDE (fmaxf(fabsf(posx), fmaxf(fabsf(posy), fabsf(posz))) < 1.0f)
        #define ADV do { posx = __fadd_rn(posx, stepx); \
                         posy = __fadd_rn(posy, stepy); \
                         posz = __fadd_rn(posz, stepz); } while (0)

        // index+weights+my-plane loads (both lanes of a pair compute
        // identical indices/weights; loads differ only by zoff)
        #define PREP_LOAD(wx_, wy_, wz_, buf_) do {                          \
            float gx_ = (posx + 1.0f) * scaleD;                              \
            float gy_ = (posy + 1.0f) * scaleD;                              \
            float gz_ = (posz + 1.0f) * scaleD;                              \
            int x0_ = min((int)gx_, Dm2);                                    \
            int y0_ = min((int)gy_, Dm2);                                    \
            int z0_ = min((int)gz_, Dm2);                                    \
            wx_ = gx_ - (float)x0_;                                          \
            wy_ = gy_ - (float)y0_;                                          \
            wz_ = gz_ - (float)z0_;                                          \
            buf_ = load_plane(g, vb + z0_ * D2 + y0_ * D + x0_ + zoff, D);   \
        } while (0)

        // consume: bilinear my plane, swap with partner, z-lerp, composite
        #define COMPOSITE(buf_, wx_, wy_, wz_) do {                          \
            __half2 tx_ = __float2half2_rn(wx_);                             \
            __half2 ty_ = __float2half2_rn(wy_);                             \
            __half2 tz_ = __float2half2_rn(wz_);                             \
            H4 mine_ = bilerp(buf_, tx_, ty_);                               \
            unsigned mlo_ = *reinterpret_cast<unsigned*>(&mine_.lo);         \
            unsigned mhi_ = *reinterpret_cast<unsigned*>(&mine_.hi);         \
            unsigned am_ = __activemask();                                   \
            unsigned tlo_ = __shfl_xor_sync(am_, mlo_, 1);                   \
            unsigned thi_ = __shfl_xor_sync(am_, mhi_, 1);                   \
            H4 theirs_;                                                      \
            theirs_.lo = *reinterpret_cast<__half2*>(&tlo_);                 \
            theirs_.hi = *reinterpret_cast<__half2*>(&thi_);                 \
            H4 c0_ = zpl ? theirs_ : mine_;                                  \
            H4 c1_ = zpl ? mine_ : theirs_;                                  \
            H4 rr_ = lerpH(c0_, c1_, tz_);                                   \
            float2 f01_ = __half22float2(rr_.lo);                            \
            float2 f23_ = __half22float2(rr_.hi);                            \
            float contrib_ = fminf(alpha + f23_.y * DTSTEP, 1.0f) - alpha;   \
            r0 += f01_.x * contrib_;                                         \
            r1 += f01_.y * contrib_;                                         \
            r2 += f23_.x * contrib_;                                         \
            alpha += contrib_;                                               \
        } while (0)

        // entry scan: positions monotone per axis -> valid region contiguous
        int s = 0;
        bool valid = INSIDE;
        while (!valid && (s + 1) < nsteps) {
            ADV;
            ++s;
            valid = INSIDE;
        }

        if (valid) {
            float cwx, cwy, cwz, nwx, nwy, nwz;
            Plane cur, nxt;
            PREP_LOAD(cwx, cwy, cwz, cur);

            for (;;) {
                // advance + prefetch next step BEFORE consuming cur
                ADV; ++s;
                bool vnext = (s < nsteps) && INSIDE;
                if (vnext) PREP_LOAD(nwx, nwy, nwz, nxt);

                COMPOSITE(cur, cwx, cwy, cwz);

                // saturation: all remaining contribs sum to <= 1e-6 (absolute)
                if (!vnext || (1.0f - alpha < 1e-6f)) break;
                cur = nxt; cwx = nwx; cwy = nwy; cwz = nwz;
            }
        }
        #undef INSIDE
        #undef ADV
        #undef PREP_LOAD
        #undef COMPOSITE
    }

    if (zpl == 0) {
        out[obase + 0 * cstr] = r0;
        out[obase + 1 * cstr] = r1;
        out[obase + 2 * cstr] = r2;
        out[obase + 3 * cstr] = alpha;
    }
}

// ---------------------------------------------------------------------------
// Launch
// ---------------------------------------------------------------------------
extern "C" void kernel_launch(void* const* d_in, const int* in_sizes, int n_in,
                              void* d_out, int out_size) {
    const float* camrot  = (const float*)d_in[0];
    const float* campos  = (const float*)d_in[1];
    const float* focal   = (const float*)d_in[2];
    const float* princpt = (const float*)d_in[3];
    const float* pix     = (const float*)d_in[4];
    const float* volume  = (const float*)d_in[5];
    float* out = (float*)d_out;

    int B = in_sizes[1] / 3;
    int hw = in_sizes[4] / (2 * B);
    int H = (int)(sqrt((double)hw) + 0.5);
    int W = H;
    int d3 = in_sizes[5] / (4 * B);
    int D = (int)(cbrt((double)d3) + 0.5);
    int nsteps = (int)ceil(2.0 * sqrt(3.0) / 0.03125);  // 111

    int ngroups = B * (d3 / 4);
    permute_half_kernel<<<(ngroups + 255) / 256, 256>>>(
        (const float4*)volume, B, d3);

    // 64 threads/x-dim = 32 pixels (2 threads per pixel), 4 rows -> 256 thr
    dim3 block(64, 4, 1);
    dim3 grid((W + 31) / 32, (H + 3) / 4, B);
    raymarch_kernel<<<grid, block>>>(camrot, campos, focal, princpt, pix,
                                     out, B, H, W, D, nsteps);
}